// round 2
// baseline (speedup 1.0000x reference)
#include <cuda_runtime.h>

// Problem constants
#define B_CH   256
#define CH     32
#define B      8          // B_CH / CH
#define H      8
#define E      64
#define L      32         // patch_num = WIN/p
#define P      8          // patch size
#define WIN    256

// Scratch: channel-mean softmax scores
__device__ float g_ps[B * H * L * L];   // 65536 floats
__device__ float g_pn[B * H * P * P];   // 4096 floats

// ---------------------------------------------------------------------------
// Kernel 0: zero the scratch accumulators (graph replays re-use them)
// ---------------------------------------------------------------------------
__global__ void zero_scratch_kernel() {
    int idx = blockIdx.x * blockDim.x + threadIdx.x;
    if (idx < B * H * L * L) g_ps[idx] = 0.0f;
    if (idx < B * H * P * P) g_pn[idx] = 0.0f;
}

// ---------------------------------------------------------------------------
// Kernel 1: patch_size branch. One block per (bc, h).
// Block = 128 threads = 4 warps; warp w computes rows [8w, 8w+8) of the 32x32
// score tile, lane = column. Softmax per row via warp shuffles, then
// atomicAdd of value/CH into g_ps (channel mean).
// ---------------------------------------------------------------------------
__global__ __launch_bounds__(128) void attn_ps_kernel(
    const float* __restrict__ q, const float* __restrict__ k)
{
    const int bc = blockIdx.x >> 3;
    const int h  = blockIdx.x & 7;

    __shared__ float4 qs[L * 16];       // [row][e4], broadcast-read
    __shared__ float4 ks[L * 17];       // [col][e4] pad to 17 -> conflict-free

    // q[bc, l, h, e] at bc*L*H*E + l*H*E + h*E + e
    const float* qb = q + (size_t)bc * (L * H * E) + h * E;
    const float* kb = k + (size_t)bc * (L * H * E) + h * E;

    for (int i = threadIdx.x; i < 2 * L * 16; i += 128) {
        int which = i >> 9;             // 0: q, 1: k
        int r     = (i >> 4) & (L - 1);
        int e4    = i & 15;
        if (which == 0) {
            qs[r * 16 + e4] = ((const float4*)(qb + r * H * E))[e4];
        } else {
            ks[r * 17 + e4] = ((const float4*)(kb + r * H * E))[e4];
        }
    }
    __syncthreads();

    const int warp = threadIdx.x >> 5;
    const int lane = threadIdx.x & 31;  // = column
    float acc[8];
#pragma unroll
    for (int r = 0; r < 8; ++r) acc[r] = 0.0f;

#pragma unroll
    for (int e4 = 0; e4 < 16; ++e4) {
        float4 kv = ks[lane * 17 + e4];
#pragma unroll
        for (int r = 0; r < 8; ++r) {
            float4 qv = qs[(warp * 8 + r) * 16 + e4];
            acc[r] += qv.x * kv.x + qv.y * kv.y + qv.z * kv.z + qv.w * kv.w;
        }
    }

    const int bb = bc >> 5;             // b = bc / CH (channel is inner dim)
    float* dst = g_ps + (((bb * H + h) * L) + warp * 8) * L;

#pragma unroll
    for (int r = 0; r < 8; ++r) {
        float s = acc[r] * 0.125f;      // 1/sqrt(E)
        float m = s;
#pragma unroll
        for (int o = 16; o > 0; o >>= 1)
            m = fmaxf(m, __shfl_xor_sync(0xffffffffu, m, o));
        float ev = __expf(s - m);
        float sum = ev;
#pragma unroll
        for (int o = 16; o > 0; o >>= 1)
            sum += __shfl_xor_sync(0xffffffffu, sum, o);
        atomicAdd(dst + r * L + lane, ev * (1.0f / (float)CH) / sum);
    }
}

// ---------------------------------------------------------------------------
// Kernel 2: patch_num branch. One block per bc, 512 threads.
// thread = h*64 + r*8 + j computes score(r, j) for head h; softmax over j
// (aligned groups of 8 lanes -> segmented shuffles).
// ---------------------------------------------------------------------------
__global__ __launch_bounds__(512) void attn_pn_kernel(
    const float* __restrict__ q, const float* __restrict__ k)
{
    const int bc = blockIdx.x;

    __shared__ float4 qs4[P * H * 16];        // contiguous copy of q slice
    __shared__ float4 ks4[P * 129];           // per-j stride 129 f4 (=516 f)

    const float* qb = q + (size_t)bc * (P * H * E);
    const float* kb = k + (size_t)bc * (P * H * E);

    // whole (p, H, E) slice is contiguous: 1024 float4 each
    for (int i = threadIdx.x; i < 1024; i += 512) {
        qs4[i] = ((const float4*)qb)[i];
        int j = i >> 7;                        // key index
        int rest = i & 127;                    // h*16 + e4
        ks4[j * 129 + rest] = ((const float4*)kb)[i];
    }
    __syncthreads();

    const int t  = threadIdx.x;
    const int hh = t >> 6;
    const int r  = (t >> 3) & 7;
    const int j  = t & 7;

    float acc = 0.0f;
#pragma unroll
    for (int e4 = 0; e4 < 16; ++e4) {
        float4 qv = qs4[(r * H + hh) * 16 + e4];
        float4 kv = ks4[j * 129 + hh * 16 + e4];
        acc += qv.x * kv.x + qv.y * kv.y + qv.z * kv.z + qv.w * kv.w;
    }

    float s = acc * 0.125f;
    float m = s;
#pragma unroll
    for (int o = 4; o > 0; o >>= 1)
        m = fmaxf(m, __shfl_xor_sync(0xffffffffu, m, o));
    float ev = __expf(s - m);
    float sum = ev;
#pragma unroll
    for (int o = 4; o > 0; o >>= 1)
        sum += __shfl_xor_sync(0xffffffffu, sum, o);

    const int bb = bc >> 5;
    atomicAdd(g_pn + (((bb * H + hh) * P) + r) * P + j,
              ev * (1.0f / (float)CH) / sum);
}

// ---------------------------------------------------------------------------
// Kernel 3: expansion writes. Each thread writes one float4 of s_ps (splat,
// element-repeat by 8x8) and one float4 of s_pn (tile by 32x32).
// ---------------------------------------------------------------------------
__global__ __launch_bounds__(256) void expand_kernel(float* __restrict__ out)
{
    const int idx = blockIdx.x * 256 + threadIdx.x;   // float4 index, 0..2M-1
    float4* o4 = (float4*)out;

    const int j4 = idx & 63;            // float4-column within 256-wide row
    const int i  = (idx >> 6) & 255;    // row within WIN
    const int bh = idx >> 14;           // 0..63

    // s_ps: repeat each [32x32] element 8x8
    float v = g_ps[(bh * L + (i >> 3)) * L + (j4 >> 1)];
    o4[idx] = make_float4(v, v, v, v);

    // s_pn: tile [8x8] 32x32 times; a float4 is an aligned half of a pn row
    const float4* pn4 = (const float4*)g_pn;
    o4[idx + (B * H * WIN * WIN / 4)] =
        pn4[(bh * P + (i & 7)) * 2 + (j4 & 1)];
}

// ---------------------------------------------------------------------------
extern "C" void kernel_launch(void* const* d_in, const int* in_sizes, int n_in,
                              void* d_out, int out_size)
{
    const float* q_ps = (const float*)d_in[0];
    const float* k_ps = (const float*)d_in[1];
    const float* q_pn = (const float*)d_in[2];
    const float* k_pn = (const float*)d_in[3];
    float* out = (float*)d_out;

    zero_scratch_kernel<<<(B * H * L * L + 255) / 256, 256>>>();
    attn_ps_kernel<<<B_CH * H, 128>>>(q_ps, k_ps);
    attn_pn_kernel<<<B_CH, 512>>>(q_pn, k_pn);
    expand_kernel<<<(B * H * WIN * WIN / 4) / 256, 256>>>(out);
}